// round 3
// baseline (speedup 1.0000x reference)
#include <cuda_runtime.h>

// Affine-collapse: weight(x) = alpha*x + beta (4-layer affine MLP, no activations).
// out[row] = alpha * S2/S1^2 + beta, S1 = sum(x), S2 = sum(x^2), row = 2048 floats.
//
// 2 rows per 256-thread CTA: 128 threads per row, 4 front-batched float4 loads
// each. High occupancy (8 CTAs/SM) + MLP_p1=4. Warp 0 recomputes (alpha, beta)
// from the tiny weight tensors while the row loads are in flight.

#define HIDDEN 32
#define L 2048
#define L_VEC4 (L / 4)   // 512 float4 per row
#define ROWS_PER_CTA 2
#define THREADS 256

__global__ __launch_bounds__(THREADS, 8) void incidence_fused_kernel(
    const float4* __restrict__ x,
    const float* __restrict__ w1, const float* __restrict__ b1,
    const float* __restrict__ w2, const float* __restrict__ b2,
    const float* __restrict__ w3, const float* __restrict__ b3,
    const float* __restrict__ w4, const float* __restrict__ b4,
    float* __restrict__ out)
{
    __shared__ float sh1[8], sh2[8];
    __shared__ float sh_alpha, sh_beta;

    const int t    = threadIdx.x;
    const int wid  = t >> 5;
    const int lid  = t & 31;
    const int rloc = t >> 7;        // 0 or 1: which of the CTA's two rows
    const int c    = t & 127;       // lane within the row's 128-thread group
    const int row  = blockIdx.x * ROWS_PER_CTA + rloc;

    // ---- front-batch all 4 independent LDG.128s ----
    const float4* __restrict__ p = x + (size_t)row * L_VEC4 + c;
    const float4 v0 = p[0 * 128];
    const float4 v1 = p[1 * 128];
    const float4 v2 = p[2 * 128];
    const float4 v3 = p[3 * 128];

    // ---- warp 0: collapse the affine stack into (alpha, beta) while the
    //      row loads are in flight (weights are tiny; L2-resident) ----
    if (wid == 0) {
        const unsigned m = 0xffffffffu;
        float va = w1[lid];
        float ca = b1[lid];

        float sv = 0.f, sc = 0.f;
        #pragma unroll
        for (int i = 0; i < HIDDEN; i++) {
            const float w = w2[i * HIDDEN + lid];
            sv += __shfl_sync(m, va, i) * w;
            sc += __shfl_sync(m, ca, i) * w;
        }
        const float vb = sv;
        const float cb = sc + b2[lid];

        sv = 0.f; sc = 0.f;
        #pragma unroll
        for (int i = 0; i < HIDDEN; i++) {
            const float w = w3[i * HIDDEN + lid];
            sv += __shfl_sync(m, vb, i) * w;
            sc += __shfl_sync(m, cb, i) * w;
        }
        const float vc = sv;
        const float cc = sc + b3[lid];

        float a = vc * w4[lid];
        float b = cc * w4[lid];
        #pragma unroll
        for (int off = 16; off > 0; off >>= 1) {
            a += __shfl_xor_sync(m, a, off);
            b += __shfl_xor_sync(m, b, off);
        }
        if (lid == 0) {
            sh_alpha = a;
            sh_beta  = b + b4[0];
        }
    }

    // ---- consume loads: per-thread partial sums ----
    float s1, s2;
    s1  = (v0.x + v0.y) + (v0.z + v0.w);
    s2  = v0.x * v0.x + v0.y * v0.y + v0.z * v0.z + v0.w * v0.w;
    s1 += (v1.x + v1.y) + (v1.z + v1.w);
    s2 += v1.x * v1.x + v1.y * v1.y + v1.z * v1.z + v1.w * v1.w;
    s1 += (v2.x + v2.y) + (v2.z + v2.w);
    s2 += v2.x * v2.x + v2.y * v2.y + v2.z * v2.z + v2.w * v2.w;
    s1 += (v3.x + v3.y) + (v3.z + v3.w);
    s2 += v3.x * v3.x + v3.y * v3.y + v3.z * v3.z + v3.w * v3.w;

    // warp reduce
    #pragma unroll
    for (int off = 16; off > 0; off >>= 1) {
        s1 += __shfl_xor_sync(0xffffffffu, s1, off);
        s2 += __shfl_xor_sync(0xffffffffu, s2, off);
    }
    if (lid == 0) { sh1[wid] = s1; sh2[wid] = s2; }

    __syncthreads();  // publishes sh1/sh2 AND sh_alpha/sh_beta

    // ---- final combine: one thread per row (warps 0-3 = row0, 4-7 = row1) ----
    if (c == 0) {  // t == 0 and t == 128
        const int base = rloc * 4;
        const float a1 = (sh1[base + 0] + sh1[base + 1]) + (sh1[base + 2] + sh1[base + 3]);
        const float a2 = (sh2[base + 0] + sh2[base + 1]) + (sh2[base + 2] + sh2[base + 3]);
        out[row] = sh_alpha * a2 / (a1 * a1) + sh_beta;
    }
}

extern "C" void kernel_launch(void* const* d_in, const int* in_sizes, int n_in,
                              void* d_out, int out_size) {
    const float* inc_m = (const float*)d_in[0];
    const float* w1 = (const float*)d_in[1];
    const float* b1 = (const float*)d_in[2];
    const float* w2 = (const float*)d_in[3];
    const float* b2 = (const float*)d_in[4];
    const float* w3 = (const float*)d_in[5];
    const float* b3 = (const float*)d_in[6];
    const float* w4 = (const float*)d_in[7];
    const float* b4 = (const float*)d_in[8];
    float* out = (float*)d_out;

    const int rows = in_sizes[0] / L;          // B*F = 2048 (even)
    const int blocks = rows / ROWS_PER_CTA;    // 1024

    incidence_fused_kernel<<<blocks, THREADS>>>(
        (const float4*)inc_m, w1, b1, w2, b2, w3, b3, w4, b4, out);
}

// round 4
// speedup vs baseline: 1.6855x; 1.6855x over previous
#include <cuda_runtime.h>

// Affine-collapse: weight(x) = alpha*x + beta (4-layer affine MLP, no activations).
// out[row] = alpha * S2/S1^2 + beta, S1 = sum(x), S2 = sum(x^2), row = 2048 floats.
//
// 2 rows per 256-thread CTA (128 threads/row, 4 front-batched float4 loads each).
// grid = 1024 -> ~one wave across 148 SMs, no CTA churn. Warp 0 recomputes
// (alpha, beta) from the tiny L2-resident weights while row loads are in flight.
// NO min-blocks launch_bounds: the R3 regression came from the reg cap
// serializing the weight loads.

#define HIDDEN 32
#define L 2048
#define L_VEC4 (L / 4)   // 512 float4 per row
#define ROWS_PER_CTA 2
#define THREADS 256

__global__ __launch_bounds__(THREADS) void incidence_fused_kernel(
    const float4* __restrict__ x,
    const float* __restrict__ w1, const float* __restrict__ b1,
    const float* __restrict__ w2, const float* __restrict__ b2,
    const float* __restrict__ w3, const float* __restrict__ b3,
    const float* __restrict__ w4, const float* __restrict__ b4,
    float* __restrict__ out, int rows)
{
    __shared__ float sh1[8], sh2[8];
    __shared__ float sh_alpha, sh_beta;

    const int t    = threadIdx.x;
    const int wid  = t >> 5;
    const int lid  = t & 31;
    const int rloc = t >> 7;        // 0 or 1: which of the CTA's two rows
    const int c    = t & 127;       // lane within the row's 128-thread group
    const int row  = blockIdx.x * ROWS_PER_CTA + rloc;
    const bool live = (row < rows);

    // ---- front-batch the 4 independent LDG.128s for this thread's row slice ----
    float4 v0, v1, v2, v3;
    if (live) {
        const float4* __restrict__ p = x + (size_t)row * L_VEC4 + c;
        v0 = p[0 * 128];
        v1 = p[1 * 128];
        v2 = p[2 * 128];
        v3 = p[3 * 128];
    } else {
        v0 = v1 = v2 = v3 = make_float4(0.f, 0.f, 0.f, 0.f);
    }

    // ---- warp 0: collapse the affine stack into (alpha, beta) while the
    //      row loads are in flight. Loops split in halves of 16 so the weight
    //      loads batch into flight without huge register pressure. ----
    if (wid == 0) {
        const unsigned m = 0xffffffffu;
        const float va = w1[lid];
        const float ca = b1[lid];

        float sv = 0.f, sc = 0.f;
        {
            float wr[16];
            #pragma unroll
            for (int i = 0; i < 16; i++) wr[i] = w2[i * HIDDEN + lid];
            #pragma unroll
            for (int i = 0; i < 16; i++) {
                sv += __shfl_sync(m, va, i) * wr[i];
                sc += __shfl_sync(m, ca, i) * wr[i];
            }
            #pragma unroll
            for (int i = 0; i < 16; i++) wr[i] = w2[(i + 16) * HIDDEN + lid];
            #pragma unroll
            for (int i = 0; i < 16; i++) {
                sv += __shfl_sync(m, va, i + 16) * wr[i];
                sc += __shfl_sync(m, ca, i + 16) * wr[i];
            }
        }
        const float vb = sv;
        const float cb = sc + b2[lid];

        sv = 0.f; sc = 0.f;
        {
            float wr[16];
            #pragma unroll
            for (int i = 0; i < 16; i++) wr[i] = w3[i * HIDDEN + lid];
            #pragma unroll
            for (int i = 0; i < 16; i++) {
                sv += __shfl_sync(m, vb, i) * wr[i];
                sc += __shfl_sync(m, cb, i) * wr[i];
            }
            #pragma unroll
            for (int i = 0; i < 16; i++) wr[i] = w3[(i + 16) * HIDDEN + lid];
            #pragma unroll
            for (int i = 0; i < 16; i++) {
                sv += __shfl_sync(m, vb, i + 16) * wr[i];
                sc += __shfl_sync(m, cb, i + 16) * wr[i];
            }
        }
        const float vc = sv;
        const float cc = sc + b3[lid];

        float a = vc * w4[lid];
        float b = cc * w4[lid];
        #pragma unroll
        for (int off = 16; off > 0; off >>= 1) {
            a += __shfl_xor_sync(m, a, off);
            b += __shfl_xor_sync(m, b, off);
        }
        if (lid == 0) {
            sh_alpha = a;
            sh_beta  = b + b4[0];
        }
    }

    // ---- consume the row loads: per-thread partial sums ----
    float s1, s2;
    s1  = (v0.x + v0.y) + (v0.z + v0.w);
    s2  = v0.x * v0.x + v0.y * v0.y + v0.z * v0.z + v0.w * v0.w;
    s1 += (v1.x + v1.y) + (v1.z + v1.w);
    s2 += v1.x * v1.x + v1.y * v1.y + v1.z * v1.z + v1.w * v1.w;
    s1 += (v2.x + v2.y) + (v2.z + v2.w);
    s2 += v2.x * v2.x + v2.y * v2.y + v2.z * v2.z + v2.w * v2.w;
    s1 += (v3.x + v3.y) + (v3.z + v3.w);
    s2 += v3.x * v3.x + v3.y * v3.y + v3.z * v3.z + v3.w * v3.w;

    // warp reduce
    #pragma unroll
    for (int off = 16; off > 0; off >>= 1) {
        s1 += __shfl_xor_sync(0xffffffffu, s1, off);
        s2 += __shfl_xor_sync(0xffffffffu, s2, off);
    }
    if (lid == 0) { sh1[wid] = s1; sh2[wid] = s2; }

    __syncthreads();  // publishes sh1/sh2 AND sh_alpha/sh_beta

    // ---- final combine: one thread per row (t==0 -> row0, t==128 -> row1) ----
    if (c == 0 && live) {
        const int base = rloc * 4;
        const float a1 = (sh1[base + 0] + sh1[base + 1]) + (sh1[base + 2] + sh1[base + 3]);
        const float a2 = (sh2[base + 0] + sh2[base + 1]) + (sh2[base + 2] + sh2[base + 3]);
        out[row] = sh_alpha * a2 / (a1 * a1) + sh_beta;
    }
}

extern "C" void kernel_launch(void* const* d_in, const int* in_sizes, int n_in,
                              void* d_out, int out_size) {
    const float* inc_m = (const float*)d_in[0];
    const float* w1 = (const float*)d_in[1];
    const float* b1 = (const float*)d_in[2];
    const float* w2 = (const float*)d_in[3];
    const float* b2 = (const float*)d_in[4];
    const float* w3 = (const float*)d_in[5];
    const float* b3 = (const float*)d_in[6];
    const float* w4 = (const float*)d_in[7];
    const float* b4 = (const float*)d_in[8];
    float* out = (float*)d_out;

    const int rows = in_sizes[0] / L;                       // B*F = 2048
    const int blocks = (rows + ROWS_PER_CTA - 1) / ROWS_PER_CTA;  // 1024

    incidence_fused_kernel<<<blocks, THREADS>>>(
        (const float4*)inc_m, w1, b1, w2, b2, w3, b3, w4, b4, out, rows);
}